// round 8
// baseline (speedup 1.0000x reference)
#include <cuda_runtime.h>
#include <math.h>
#include <stdint.h>

#define BATCH 4
#define SEQ   2048
#define DIM   2048
#define NH    16
#define DHEAD 128
#define MTOT  (BATCH * SEQ)

// Scratch (allocation-free rule: __device__ globals)
__device__ float g_Q[BATCH * SEQ * DIM];
__device__ float g_K[BATCH * SEQ * DIM];
__device__ float g_V[BATCH * SEQ * DIM];
__device__ float g_A[BATCH * SEQ * DIM];
__device__ float g_X[MTOT * DIM];        // tf32-rounded x
__device__ float g_W[DIM * DIM];         // tf32-rounded weight (reused serially)

__device__ __forceinline__ unsigned f2tf32(float x) {
    unsigned u;
    asm("cvt.rna.tf32.f32 %0, %1;" : "=r"(u) : "f"(x));
    return u;
}
__device__ __forceinline__ uint32_t smem_u32(const void* p) {
    uint32_t a;
    asm("{ .reg .u64 t; cvta.to.shared.u64 t, %1; cvt.u32.u64 %0, t; }" : "=r"(a) : "l"(p));
    return a;
}
__device__ __forceinline__ void mma_tf32(float* d, const unsigned* a, const unsigned* b) {
    asm volatile(
        "mma.sync.aligned.m16n8k8.row.col.f32.tf32.tf32.f32 "
        "{%0,%1,%2,%3}, {%4,%5,%6,%7}, {%8,%9}, {%0,%1,%2,%3};\n"
        : "+f"(d[0]), "+f"(d[1]), "+f"(d[2]), "+f"(d[3])
        : "r"(a[0]), "r"(a[1]), "r"(a[2]), "r"(a[3]), "r"(b[0]), "r"(b[1]));
}
__device__ __forceinline__ void cp16(uint32_t dst, const void* src) {
    asm volatile("cp.async.cg.shared.global [%0], [%1], 16;" :: "r"(dst), "l"(src));
}

// ---------------------------------------------------------------------------
// elementwise tf32-RNA rounding
// ---------------------------------------------------------------------------
__global__ __launch_bounds__(256) void round_tf32_kernel(
    const float* __restrict__ in, float* __restrict__ out, int n4)
{
    int i = blockIdx.x * blockDim.x + threadIdx.x;
    if (i >= n4) return;
    float4 v = ((const float4*)in)[i];
    uint4 u = make_uint4(f2tf32(v.x), f2tf32(v.y), f2tf32(v.z), f2tf32(v.w));
    ((uint4*)out)[i] = u;
}

// ---------------------------------------------------------------------------
// TF32 NT GEMM, 4-stage cp.async pipeline. Inputs MUST be tf32-pre-rounded.
// C = (A @ W^T + bias) * gate ; tiles 128x128x32, 256 threads, 8 warps.
// ---------------------------------------------------------------------------
#define GSTRIDE 36
#define STG_ELEMS (128 * GSTRIDE)            // one matrix, one stage
#define NSTAGES 4
#define GEMM_SMEM_BYTES (NSTAGES * 2 * STG_ELEMS * 4)   // 147456

__global__ __launch_bounds__(256) void gemm_tf32_kernel(
    const float* __restrict__ A, const float* __restrict__ W,
    const float* __restrict__ bias, const float* __restrict__ rot,
    int mode, int roundout, float* __restrict__ C)
{
    extern __shared__ unsigned sm[];
    const int K = DIM, N = DIM;
    const int tid = threadIdx.x;
    const int warp = tid >> 5, lane = tid & 31;
    const int wm = (warp >> 2) * 64;
    const int wn = (warp & 3) * 32;
    const int bm = blockIdx.y * 128, bn = blockIdx.x * 128;
    const int lq = lane >> 2, lr = lane & 3;

    const int row = tid >> 1;                 // 0..127
    const int ch0 = (tid & 1) * 4;            // 16B chunks 0-3 / 4-7

    const uint32_t sbase = smem_u32(sm);
    const float* Ag = A + (size_t)(bm + row) * K + ch0 * 4;
    const float* Wg = W + (size_t)(bn + row) * K + ch0 * 4;

    float acc[4][4][4];
#pragma unroll
    for (int i = 0; i < 4; i++)
#pragma unroll
        for (int j = 0; j < 4; j++)
#pragma unroll
            for (int t = 0; t < 4; t++) acc[i][j][t] = 0.f;

    auto issue = [&](int kt, int stg) {
        const uint32_t as = sbase + (stg * 2 * STG_ELEMS + row * GSTRIDE + ch0 * 4) * 4;
        const uint32_t bs = as + STG_ELEMS * 4;
        const size_t ko = (size_t)kt * 32;
#pragma unroll
        for (int i = 0; i < 4; i++) {
            cp16(as + i * 16, Ag + ko + i * 4);
            cp16(bs + i * 16, Wg + ko + i * 4);
        }
        asm volatile("cp.async.commit_group;");
    };

    const int ntiles = K / 32;               // 64
    issue(0, 0); issue(1, 1); issue(2, 2);

    for (int kt = 0; kt < ntiles; kt++) {
        if (kt < ntiles - 2)      asm volatile("cp.async.wait_group 2;");
        else if (kt == ntiles - 2) asm volatile("cp.async.wait_group 1;");
        else                       asm volatile("cp.async.wait_group 0;");
        __syncthreads();

        if (kt + 3 < ntiles) issue(kt + 3, (kt + 3) & (NSTAGES - 1));

        const unsigned* Ab = sm + (kt & (NSTAGES - 1)) * 2 * STG_ELEMS;
        const unsigned* Bb = Ab + STG_ELEMS;
#pragma unroll
        for (int k8 = 0; k8 < 4; k8++) {
            const int kc = k8 * 8 + lr;
            unsigned af[4][4], bf[4][2];
#pragma unroll
            for (int i = 0; i < 4; i++) {
                int r = wm + i * 16 + lq;
                af[i][0] = Ab[r * GSTRIDE + kc];
                af[i][1] = Ab[(r + 8) * GSTRIDE + kc];
                af[i][2] = Ab[r * GSTRIDE + kc + 4];
                af[i][3] = Ab[(r + 8) * GSTRIDE + kc + 4];
            }
#pragma unroll
            for (int j = 0; j < 4; j++) {
                int c = wn + j * 8 + lq;
                bf[j][0] = Bb[c * GSTRIDE + kc];
                bf[j][1] = Bb[c * GSTRIDE + kc + 4];
            }
#pragma unroll
            for (int i = 0; i < 4; i++)
#pragma unroll
                for (int j = 0; j < 4; j++)
                    mma_tf32(acc[i][j], af[i], bf[j]);
        }
    }

    // epilogue: bias + optional cos/sin gate, optional tf32 rounding
#pragma unroll
    for (int j = 0; j < 4; j++) {
        int c0 = bn + wn + j * 8 + (lr << 1);
        float b0 = __ldg(bias + c0), b1 = __ldg(bias + c0 + 1);
        float g0 = 1.f, g1 = 1.f;
        if (mode == 1) { g0 = cosf(__ldg(rot + c0)); g1 = cosf(__ldg(rot + c0 + 1)); }
        else if (mode == 2) { g0 = sinf(__ldg(rot + c0)); g1 = sinf(__ldg(rot + c0 + 1)); }
#pragma unroll
        for (int i = 0; i < 4; i++) {
            int r0 = bm + wm + i * 16 + lq;
            float v00 = (acc[i][j][0] + b0) * g0, v01 = (acc[i][j][1] + b1) * g1;
            float v10 = (acc[i][j][2] + b0) * g0, v11 = (acc[i][j][3] + b1) * g1;
            if (roundout) {
                v00 = __uint_as_float(f2tf32(v00)); v01 = __uint_as_float(f2tf32(v01));
                v10 = __uint_as_float(f2tf32(v10)); v11 = __uint_as_float(f2tf32(v11));
            }
            *(float2*)(C + (size_t)r0 * N + c0)       = make_float2(v00, v01);
            *(float2*)(C + (size_t)(r0 + 8) * N + c0) = make_float2(v10, v11);
        }
    }
}

// ---------------------------------------------------------------------------
// TF32 mma.sync flash attention (R5 known-good; output now tf32-rounded)
// ---------------------------------------------------------------------------
#define KSTRIDE 132
#define FLASH_SMEM_BYTES (2 * 64 * KSTRIDE * 4)

__global__ __launch_bounds__(128) void flash_tf32_kernel(
    const float* __restrict__ Q, const float* __restrict__ K,
    const float* __restrict__ V, const float* __restrict__ spiral,
    float* __restrict__ O)
{
    extern __shared__ float fs[];
    float* sK = fs;
    float* sV = fs + 64 * KSTRIDE;

    const int tid = threadIdx.x;
    const int warp = tid >> 5, lane = tid & 31;
    const int lq = lane >> 2, lr = lane & 3;
    const int qt = blockIdx.x, h = blockIdx.y, b = blockIdx.z;
    const int s0 = qt * 64;
    const float scale = spiral[h] * 0.08838834764831845f;

    const size_t baseQ = ((size_t)b * SEQ + s0) * DIM + (size_t)h * DHEAD;
    const size_t baseK = (size_t)b * SEQ * DIM + (size_t)h * DHEAD;

    for (int idx = tid; idx < 64 * 32; idx += 128) {
        int r = idx >> 5, c4 = (idx & 31) << 2;
        *(float4*)(sK + r * KSTRIDE + c4) =
            *(const float4*)(Q + baseQ + (size_t)r * DIM + c4);
    }
    __syncthreads();

    unsigned qf[16][4];
    const int qrow = warp * 16 + lq;
#pragma unroll
    for (int ks = 0; ks < 16; ks++) {
        qf[ks][0] = __float_as_uint(sK[qrow * KSTRIDE + ks * 8 + lr]);
        qf[ks][1] = __float_as_uint(sK[(qrow + 8) * KSTRIDE + ks * 8 + lr]);
        qf[ks][2] = __float_as_uint(sK[qrow * KSTRIDE + ks * 8 + lr + 4]);
        qf[ks][3] = __float_as_uint(sK[(qrow + 8) * KSTRIDE + ks * 8 + lr + 4]);
    }
    __syncthreads();

    float o[16][4];
#pragma unroll
    for (int jn = 0; jn < 16; jn++)
#pragma unroll
        for (int t = 0; t < 4; t++) o[jn][t] = 0.f;
    float m0 = -INFINITY, m1 = -INFINITY, l0 = 0.f, l1 = 0.f;

    for (int kt = 0; kt < SEQ / 64; kt++) {
        const size_t kb = baseK + (size_t)kt * 64 * DIM;
        for (int idx = tid; idx < 64 * 32; idx += 128) {
            int r = idx >> 5, c4 = (idx & 31) << 2;
            *(float4*)(sK + r * KSTRIDE + c4) =
                *(const float4*)(K + kb + (size_t)r * DIM + c4);
            *(float4*)(sV + r * KSTRIDE + c4) =
                *(const float4*)(V + kb + (size_t)r * DIM + c4);
        }
        __syncthreads();

        float sacc[8][4];
#pragma unroll
        for (int j = 0; j < 8; j++)
#pragma unroll
            for (int t = 0; t < 4; t++) sacc[j][t] = 0.f;

#pragma unroll
        for (int ks = 0; ks < 16; ks++) {
#pragma unroll
            for (int j = 0; j < 8; j++) {
                unsigned bf[2];
                bf[0] = __float_as_uint(sK[(j * 8 + lq) * KSTRIDE + ks * 8 + lr]);
                bf[1] = __float_as_uint(sK[(j * 8 + lq) * KSTRIDE + ks * 8 + lr + 4]);
                mma_tf32(sacc[j], qf[ks], bf);
            }
        }

        float mx0 = -INFINITY, mx1 = -INFINITY;
#pragma unroll
        for (int j = 0; j < 8; j++) {
            sacc[j][0] *= scale; sacc[j][1] *= scale;
            sacc[j][2] *= scale; sacc[j][3] *= scale;
            mx0 = fmaxf(mx0, fmaxf(sacc[j][0], sacc[j][1]));
            mx1 = fmaxf(mx1, fmaxf(sacc[j][2], sacc[j][3]));
        }
        mx0 = fmaxf(mx0, __shfl_xor_sync(0xffffffffu, mx0, 1));
        mx0 = fmaxf(mx0, __shfl_xor_sync(0xffffffffu, mx0, 2));
        mx1 = fmaxf(mx1, __shfl_xor_sync(0xffffffffu, mx1, 1));
        mx1 = fmaxf(mx1, __shfl_xor_sync(0xffffffffu, mx1, 2));

        float mn0 = fmaxf(m0, mx0), mn1 = fmaxf(m1, mx1);
        float al0 = __expf(m0 - mn0), al1 = __expf(m1 - mn1);
        m0 = mn0; m1 = mn1;

        unsigned pb[8][4];
        float sum0 = 0.f, sum1 = 0.f;
#pragma unroll
        for (int j = 0; j < 8; j++) {
            float p0 = __expf(sacc[j][0] - mn0);
            float p1 = __expf(sacc[j][1] - mn0);
            float p2 = __expf(sacc[j][2] - mn1);
            float p3 = __expf(sacc[j][3] - mn1);
            sum0 += p0 + p1; sum1 += p2 + p3;
            pb[j][0] = f2tf32(p0); pb[j][1] = f2tf32(p1);
            pb[j][2] = f2tf32(p2); pb[j][3] = f2tf32(p3);
        }
        sum0 += __shfl_xor_sync(0xffffffffu, sum0, 1);
        sum0 += __shfl_xor_sync(0xffffffffu, sum0, 2);
        sum1 += __shfl_xor_sync(0xffffffffu, sum1, 1);
        sum1 += __shfl_xor_sync(0xffffffffu, sum1, 2);
        l0 = l0 * al0 + sum0;
        l1 = l1 * al1 + sum1;

#pragma unroll
        for (int jn = 0; jn < 16; jn++) {
            o[jn][0] *= al0; o[jn][1] *= al0;
            o[jn][2] *= al1; o[jn][3] *= al1;
        }

        const int srcl = lq * 4 + (lr >> 1);
#pragma unroll
        for (int k8 = 0; k8 < 8; k8++) {
            unsigned a[4];
            unsigned t00 = __shfl_sync(0xffffffffu, pb[k8][0], srcl);
            unsigned t01 = __shfl_sync(0xffffffffu, pb[k8][1], srcl);
            unsigned t10 = __shfl_sync(0xffffffffu, pb[k8][2], srcl);
            unsigned t11 = __shfl_sync(0xffffffffu, pb[k8][3], srcl);
            unsigned u00 = __shfl_sync(0xffffffffu, pb[k8][0], srcl + 2);
            unsigned u01 = __shfl_sync(0xffffffffu, pb[k8][1], srcl + 2);
            unsigned u10 = __shfl_sync(0xffffffffu, pb[k8][2], srcl + 2);
            unsigned u11 = __shfl_sync(0xffffffffu, pb[k8][3], srcl + 2);
            a[0] = (lr & 1) ? t01 : t00;
            a[1] = (lr & 1) ? t11 : t10;
            a[2] = (lr & 1) ? u01 : u00;
            a[3] = (lr & 1) ? u11 : u10;
#pragma unroll
            for (int jn = 0; jn < 16; jn++) {
                unsigned bf[2];
                bf[0] = __float_as_uint(sV[(k8 * 8 + lr) * KSTRIDE + jn * 8 + lq]);
                bf[1] = __float_as_uint(sV[(k8 * 8 + lr + 4) * KSTRIDE + jn * 8 + lq]);
                mma_tf32(o[jn], a, bf);
            }
        }
        __syncthreads();
    }

    const float inv0 = 1.0f / l0, inv1 = 1.0f / l1;
    float* Orow0 = O + baseQ + (size_t)qrow * DIM;
    float* Orow1 = O + baseQ + (size_t)(qrow + 8) * DIM;
#pragma unroll
    for (int jn = 0; jn < 16; jn++) {
        int c = jn * 8 + 2 * lr;
        float2 a0 = make_float2(__uint_as_float(f2tf32(o[jn][0] * inv0)),
                                __uint_as_float(f2tf32(o[jn][1] * inv0)));
        float2 a1 = make_float2(__uint_as_float(f2tf32(o[jn][2] * inv1)),
                                __uint_as_float(f2tf32(o[jn][3] * inv1)));
        *(float2*)(Orow0 + c) = a0;
        *(float2*)(Orow1 + c) = a1;
    }
}

// ---------------------------------------------------------------------------
extern "C" void kernel_launch(void* const* d_in, const int* in_sizes, int n_in,
                              void* d_out, int out_size)
{
    const float* x      = (const float*)d_in[0];
    const float* Wq     = (const float*)d_in[1];
    const float* bq     = (const float*)d_in[2];
    const float* Wk     = (const float*)d_in[3];
    const float* bk     = (const float*)d_in[4];
    const float* Wv     = (const float*)d_in[5];
    const float* bv     = (const float*)d_in[6];
    const float* Wo     = (const float*)d_in[7];
    const float* bo     = (const float*)d_in[8];
    const float* spiral = (const float*)d_in[9];
    const float* rot    = (const float*)d_in[10];
    float* out = (float*)d_out;

    float *Qp, *Kp, *Vp, *Ap, *Xp, *Wp;
    cudaGetSymbolAddress((void**)&Qp, g_Q);
    cudaGetSymbolAddress((void**)&Kp, g_K);
    cudaGetSymbolAddress((void**)&Vp, g_V);
    cudaGetSymbolAddress((void**)&Ap, g_A);
    cudaGetSymbolAddress((void**)&Xp, g_X);
    cudaGetSymbolAddress((void**)&Wp, g_W);

    const int M = BATCH * SEQ;
    dim3 gg(DIM / 128, M / 128);
    const int xe4 = MTOT * DIM / 4, we4 = DIM * DIM / 4;

    cudaFuncSetAttribute(gemm_tf32_kernel,
                         cudaFuncAttributeMaxDynamicSharedMemorySize, GEMM_SMEM_BYTES);
    cudaFuncSetAttribute(flash_tf32_kernel,
                         cudaFuncAttributeMaxDynamicSharedMemorySize, FLASH_SMEM_BYTES);

    round_tf32_kernel<<<(xe4 + 255) / 256, 256>>>(x, Xp, xe4);

    round_tf32_kernel<<<(we4 + 255) / 256, 256>>>(Wq, Wp, we4);
    gemm_tf32_kernel<<<gg, 256, GEMM_SMEM_BYTES>>>(Xp, Wp, bq, rot, 1, 1, Qp);

    round_tf32_kernel<<<(we4 + 255) / 256, 256>>>(Wk, Wp, we4);
    gemm_tf32_kernel<<<gg, 256, GEMM_SMEM_BYTES>>>(Xp, Wp, bk, rot, 2, 1, Kp);

    round_tf32_kernel<<<(we4 + 255) / 256, 256>>>(Wv, Wp, we4);
    gemm_tf32_kernel<<<gg, 256, GEMM_SMEM_BYTES>>>(Xp, Wp, bv, nullptr, 0, 1, Vp);

    flash_tf32_kernel<<<dim3(SEQ / 64, NH, BATCH), 128, FLASH_SMEM_BYTES>>>(
        Qp, Kp, Vp, spiral, Ap);

    round_tf32_kernel<<<(we4 + 255) / 256, 256>>>(Wo, Wp, we4);
    gemm_tf32_kernel<<<gg, 256, GEMM_SMEM_BYTES>>>(Ap, Wp, bo, nullptr, 0, 0, out);
}

// round 9
// speedup vs baseline: 1.0411x; 1.0411x over previous
#include <cuda_runtime.h>
#include <math.h>
#include <stdint.h>

#define BATCH 4
#define SEQ   2048
#define DIM   2048
#define NH    16
#define DHEAD 128
#define MTOT  (BATCH * SEQ)

// Scratch (allocation-free rule: __device__ globals)
__device__ float g_Q[BATCH * SEQ * DIM];
__device__ float g_K[BATCH * SEQ * DIM];
__device__ float g_V[BATCH * SEQ * DIM];
__device__ float g_A[BATCH * SEQ * DIM];
__device__ float g_X[MTOT * DIM];
__device__ float g_Wq[DIM * DIM];
__device__ float g_Wk[DIM * DIM];
__device__ float g_Wv[DIM * DIM];
__device__ float g_Wo[DIM * DIM];

__device__ __forceinline__ unsigned f2tf32(float x) {
    unsigned u;
    asm("cvt.rna.tf32.f32 %0, %1;" : "=r"(u) : "f"(x));
    return u;
}
__device__ __forceinline__ uint32_t smem_u32(const void* p) {
    uint32_t a;
    asm("{ .reg .u64 t; cvta.to.shared.u64 t, %1; cvt.u32.u64 %0, t; }" : "=r"(a) : "l"(p));
    return a;
}
__device__ __forceinline__ void mma_tf32(float* d, const unsigned* a, const unsigned* b) {
    asm volatile(
        "mma.sync.aligned.m16n8k8.row.col.f32.tf32.tf32.f32 "
        "{%0,%1,%2,%3}, {%4,%5,%6,%7}, {%8,%9}, {%0,%1,%2,%3};\n"
        : "+f"(d[0]), "+f"(d[1]), "+f"(d[2]), "+f"(d[3])
        : "r"(a[0]), "r"(a[1]), "r"(a[2]), "r"(a[3]), "r"(b[0]), "r"(b[1]));
}
__device__ __forceinline__ void cp16(uint32_t dst, const void* src) {
    asm volatile("cp.async.cg.shared.global [%0], [%1], 16;" :: "r"(dst), "l"(src));
}

// ---------------------------------------------------------------------------
// elementwise tf32-RNA rounding
// ---------------------------------------------------------------------------
__global__ __launch_bounds__(256) void round_tf32_kernel(
    const float* __restrict__ in, float* __restrict__ out, int n4)
{
    int i = blockIdx.x * blockDim.x + threadIdx.x;
    if (i >= n4) return;
    float4 v = ((const float4*)in)[i];
    uint4 u = make_uint4(f2tf32(v.x), f2tf32(v.y), f2tf32(v.z), f2tf32(v.w));
    ((uint4*)out)[i] = u;
}

// ---------------------------------------------------------------------------
// TF32 NT GEMM, 2-stage cp.async (73.7KB smem -> 2 CTAs/SM).
// Inputs MUST be tf32-pre-rounded. C = (A @ W^T + bias) * gate.
// Tiles 128x128x32, 256 threads, 8 warps (64x32 each).
// ---------------------------------------------------------------------------
#define GSTRIDE 36
#define STG_ELEMS (128 * GSTRIDE)
#define GEMM_SMEM_BYTES (2 * 2 * STG_ELEMS * 4)   // 73728

__global__ __launch_bounds__(256) void gemm_tf32_kernel(
    const float* __restrict__ A, const float* __restrict__ W,
    const float* __restrict__ bias, const float* __restrict__ rot,
    int mode, int roundout, float* __restrict__ C)
{
    extern __shared__ unsigned sm[];
    const int K = DIM, N = DIM;
    const int tid = threadIdx.x;
    const int warp = tid >> 5, lane = tid & 31;
    const int wm = (warp >> 2) * 64;
    const int wn = (warp & 3) * 32;
    const int bm = blockIdx.y * 128, bn = blockIdx.x * 128;
    const int lq = lane >> 2, lr = lane & 3;

    const int row = tid >> 1;                 // 0..127
    const int ch0 = (tid & 1) * 4;            // chunks 0-3 / 4-7

    const uint32_t sbase = smem_u32(sm);
    const float* Ag = A + (size_t)(bm + row) * K + ch0 * 4;
    const float* Wg = W + (size_t)(bn + row) * K + ch0 * 4;

    float acc[4][4][4];
#pragma unroll
    for (int i = 0; i < 4; i++)
#pragma unroll
        for (int j = 0; j < 4; j++)
#pragma unroll
            for (int t = 0; t < 4; t++) acc[i][j][t] = 0.f;

    auto issue = [&](int kt, int stg) {
        const uint32_t as = sbase + (stg * 2 * STG_ELEMS + row * GSTRIDE + ch0 * 4) * 4;
        const uint32_t bs = as + STG_ELEMS * 4;
        const size_t ko = (size_t)kt * 32;
#pragma unroll
        for (int i = 0; i < 4; i++) {
            cp16(as + i * 16, Ag + ko + i * 4);
            cp16(bs + i * 16, Wg + ko + i * 4);
        }
        asm volatile("cp.async.commit_group;");
    };

    const int ntiles = K / 32;               // 64
    issue(0, 0);
    issue(1, 1);

    for (int kt = 0; kt < ntiles; kt++) {
        if (kt < ntiles - 1) asm volatile("cp.async.wait_group 1;");
        else                 asm volatile("cp.async.wait_group 0;");
        __syncthreads();

        const unsigned* Ab = sm + (kt & 1) * 2 * STG_ELEMS;
        const unsigned* Bb = Ab + STG_ELEMS;
#pragma unroll
        for (int k8 = 0; k8 < 4; k8++) {
            const int kc = k8 * 8 + lr;
            unsigned af[4][4], bf[4][2];
#pragma unroll
            for (int i = 0; i < 4; i++) {
                int r = wm + i * 16 + lq;
                af[i][0] = Ab[r * GSTRIDE + kc];
                af[i][1] = Ab[(r + 8) * GSTRIDE + kc];
                af[i][2] = Ab[r * GSTRIDE + kc + 4];
                af[i][3] = Ab[(r + 8) * GSTRIDE + kc + 4];
            }
#pragma unroll
            for (int j = 0; j < 4; j++) {
                int c = wn + j * 8 + lq;
                bf[j][0] = Bb[c * GSTRIDE + kc];
                bf[j][1] = Bb[c * GSTRIDE + kc + 4];
            }
#pragma unroll
            for (int i = 0; i < 4; i++)
#pragma unroll
                for (int j = 0; j < 4; j++)
                    mma_tf32(acc[i][j], af[i], bf[j]);
        }

        if (kt + 2 < ntiles) {
            __syncthreads();             // all warps done reading stage kt&1
            issue(kt + 2, kt & 1);
        }
    }

    // epilogue: bias + optional cos/sin gate, optional tf32 rounding
#pragma unroll
    for (int j = 0; j < 4; j++) {
        int c0 = bn + wn + j * 8 + (lr << 1);
        float b0 = __ldg(bias + c0), b1 = __ldg(bias + c0 + 1);
        float g0 = 1.f, g1 = 1.f;
        if (mode == 1) { g0 = cosf(__ldg(rot + c0)); g1 = cosf(__ldg(rot + c0 + 1)); }
        else if (mode == 2) { g0 = sinf(__ldg(rot + c0)); g1 = sinf(__ldg(rot + c0 + 1)); }
#pragma unroll
        for (int i = 0; i < 4; i++) {
            int r0 = bm + wm + i * 16 + lq;
            float v00 = (acc[i][j][0] + b0) * g0, v01 = (acc[i][j][1] + b1) * g1;
            float v10 = (acc[i][j][2] + b0) * g0, v11 = (acc[i][j][3] + b1) * g1;
            if (roundout) {
                v00 = __uint_as_float(f2tf32(v00)); v01 = __uint_as_float(f2tf32(v01));
                v10 = __uint_as_float(f2tf32(v10)); v11 = __uint_as_float(f2tf32(v11));
            }
            *(float2*)(C + (size_t)r0 * N + c0)       = make_float2(v00, v01);
            *(float2*)(C + (size_t)(r0 + 8) * N + c0) = make_float2(v10, v11);
        }
    }
}

// ---------------------------------------------------------------------------
// TF32 mma.sync flash attention. BM=128 (8 warps x 16 rows), BN=64, DH=128.
// 256 threads -> 2 warps/SMSP for latency hiding.
// ---------------------------------------------------------------------------
#define KSTRIDE 132
#define FLASH_SMEM_BYTES (2 * 64 * KSTRIDE * 4)

__global__ __launch_bounds__(256) void flash_tf32_kernel(
    const float* __restrict__ Q, const float* __restrict__ K,
    const float* __restrict__ V, const float* __restrict__ spiral,
    float* __restrict__ O)
{
    extern __shared__ float fs[];
    float* sK = fs;                    // [64][132]
    float* sV = fs + 64 * KSTRIDE;     // [64][132]

    const int tid = threadIdx.x;
    const int warp = tid >> 5, lane = tid & 31;
    const int lq = lane >> 2, lr = lane & 3;
    const int qt = blockIdx.x, h = blockIdx.y, b = blockIdx.z;
    const int s0 = qt * 128;
    const float scale = spiral[h] * 0.08838834764831845f;

    const size_t baseQ = ((size_t)b * SEQ + s0) * DIM + (size_t)h * DHEAD;
    const size_t baseK = (size_t)b * SEQ * DIM + (size_t)h * DHEAD;

    // load Q rows 0..63 via sK, extract frags; then rows 64..127 via sK again
    unsigned qf[16][4];
    const int qrow = warp * 16 + lq;           // 0..127
#pragma unroll
    for (int half = 0; half < 2; half++) {
        for (int idx = tid; idx < 64 * 32; idx += 256) {
            int r = idx >> 5, c4 = (idx & 31) << 2;
            *(float4*)(sK + r * KSTRIDE + c4) =
                *(const float4*)(Q + baseQ + (size_t)(half * 64 + r) * DIM + c4);
        }
        __syncthreads();
        if ((qrow >> 6) == half) {
            int rr = qrow & 63;
#pragma unroll
            for (int ks = 0; ks < 16; ks++) {
                qf[ks][0] = __float_as_uint(sK[rr * KSTRIDE + ks * 8 + lr]);
                qf[ks][1] = __float_as_uint(sK[(rr + 8) * KSTRIDE + ks * 8 + lr]);
                qf[ks][2] = __float_as_uint(sK[rr * KSTRIDE + ks * 8 + lr + 4]);
                qf[ks][3] = __float_as_uint(sK[(rr + 8) * KSTRIDE + ks * 8 + lr + 4]);
            }
        }
        __syncthreads();
    }

    float o[16][4];
#pragma unroll
    for (int jn = 0; jn < 16; jn++)
#pragma unroll
        for (int t = 0; t < 4; t++) o[jn][t] = 0.f;
    float m0 = -INFINITY, m1 = -INFINITY, l0 = 0.f, l1 = 0.f;

    for (int kt = 0; kt < SEQ / 64; kt++) {
        const size_t kb = baseK + (size_t)kt * 64 * DIM;
        for (int idx = tid; idx < 64 * 32; idx += 256) {
            int r = idx >> 5, c4 = (idx & 31) << 2;
            *(float4*)(sK + r * KSTRIDE + c4) =
                *(const float4*)(K + kb + (size_t)r * DIM + c4);
            *(float4*)(sV + r * KSTRIDE + c4) =
                *(const float4*)(V + kb + (size_t)r * DIM + c4);
        }
        __syncthreads();

        // ---- S = Q @ K^T : per-warp 16x64 ----
        float sacc[8][4];
#pragma unroll
        for (int j = 0; j < 8; j++)
#pragma unroll
            for (int t = 0; t < 4; t++) sacc[j][t] = 0.f;

#pragma unroll
        for (int ks = 0; ks < 16; ks++) {
#pragma unroll
            for (int j = 0; j < 8; j++) {
                unsigned bf[2];
                bf[0] = __float_as_uint(sK[(j * 8 + lq) * KSTRIDE + ks * 8 + lr]);
                bf[1] = __float_as_uint(sK[(j * 8 + lq) * KSTRIDE + ks * 8 + lr + 4]);
                mma_tf32(sacc[j], qf[ks], bf);
            }
        }

        // ---- online softmax in registers ----
        float mx0 = -INFINITY, mx1 = -INFINITY;
#pragma unroll
        for (int j = 0; j < 8; j++) {
            sacc[j][0] *= scale; sacc[j][1] *= scale;
            sacc[j][2] *= scale; sacc[j][3] *= scale;
            mx0 = fmaxf(mx0, fmaxf(sacc[j][0], sacc[j][1]));
            mx1 = fmaxf(mx1, fmaxf(sacc[j][2], sacc[j][3]));
        }
        mx0 = fmaxf(mx0, __shfl_xor_sync(0xffffffffu, mx0, 1));
        mx0 = fmaxf(mx0, __shfl_xor_sync(0xffffffffu, mx0, 2));
        mx1 = fmaxf(mx1, __shfl_xor_sync(0xffffffffu, mx1, 1));
        mx1 = fmaxf(mx1, __shfl_xor_sync(0xffffffffu, mx1, 2));

        float mn0 = fmaxf(m0, mx0), mn1 = fmaxf(m1, mx1);
        float al0 = __expf(m0 - mn0), al1 = __expf(m1 - mn1);
        m0 = mn0; m1 = mn1;

        unsigned pb[8][4];
        float sum0 = 0.f, sum1 = 0.f;
#pragma unroll
        for (int j = 0; j < 8; j++) {
            float p0 = __expf(sacc[j][0] - mn0);
            float p1 = __expf(sacc[j][1] - mn0);
            float p2 = __expf(sacc[j][2] - mn1);
            float p3 = __expf(sacc[j][3] - mn1);
            sum0 += p0 + p1; sum1 += p2 + p3;
            pb[j][0] = f2tf32(p0); pb[j][1] = f2tf32(p1);
            pb[j][2] = f2tf32(p2); pb[j][3] = f2tf32(p3);
        }
        sum0 += __shfl_xor_sync(0xffffffffu, sum0, 1);
        sum0 += __shfl_xor_sync(0xffffffffu, sum0, 2);
        sum1 += __shfl_xor_sync(0xffffffffu, sum1, 1);
        sum1 += __shfl_xor_sync(0xffffffffu, sum1, 2);
        l0 = l0 * al0 + sum0;
        l1 = l1 * al1 + sum1;

#pragma unroll
        for (int jn = 0; jn < 16; jn++) {
            o[jn][0] *= al0; o[jn][1] *= al0;
            o[jn][2] *= al1; o[jn][3] *= al1;
        }

        // ---- O += P @ V (P repacked C-frag -> A-frag via shuffles) ----
        const int srcl = lq * 4 + (lr >> 1);
#pragma unroll
        for (int k8 = 0; k8 < 8; k8++) {
            unsigned a[4];
            unsigned t00 = __shfl_sync(0xffffffffu, pb[k8][0], srcl);
            unsigned t01 = __shfl_sync(0xffffffffu, pb[k8][1], srcl);
            unsigned t10 = __shfl_sync(0xffffffffu, pb[k8][2], srcl);
            unsigned t11 = __shfl_sync(0xffffffffu, pb[k8][3], srcl);
            unsigned u00 = __shfl_sync(0xffffffffu, pb[k8][0], srcl + 2);
            unsigned u01 = __shfl_sync(0xffffffffu, pb[k8][1], srcl + 2);
            unsigned u10 = __shfl_sync(0xffffffffu, pb[k8][2], srcl + 2);
            unsigned u11 = __shfl_sync(0xffffffffu, pb[k8][3], srcl + 2);
            a[0] = (lr & 1) ? t01 : t00;
            a[1] = (lr & 1) ? t11 : t10;
            a[2] = (lr & 1) ? u01 : u00;
            a[3] = (lr & 1) ? u11 : u10;
#pragma unroll
            for (int jn = 0; jn < 16; jn++) {
                unsigned bf[2];
                bf[0] = __float_as_uint(sV[(k8 * 8 + lr) * KSTRIDE + jn * 8 + lq]);
                bf[1] = __float_as_uint(sV[(k8 * 8 + lr + 4) * KSTRIDE + jn * 8 + lq]);
                mma_tf32(o[jn], a, bf);
            }
        }
        __syncthreads();
    }

    // finalize + store, tf32-rounded (next GEMM consumes raw)
    const float inv0 = 1.0f / l0, inv1 = 1.0f / l1;
    float* Orow0 = O + baseQ + (size_t)qrow * DIM;
    float* Orow1 = O + baseQ + (size_t)(qrow + 8) * DIM;
#pragma unroll
    for (int jn = 0; jn < 16; jn++) {
        int c = jn * 8 + 2 * lr;
        float2 a0 = make_float2(__uint_as_float(f2tf32(o[jn][0] * inv0)),
                                __uint_as_float(f2tf32(o[jn][1] * inv0)));
        float2 a1 = make_float2(__uint_as_float(f2tf32(o[jn][2] * inv1)),
                                __uint_as_float(f2tf32(o[jn][3] * inv1)));
        *(float2*)(Orow0 + c) = a0;
        *(float2*)(Orow1 + c) = a1;
    }
}

// ---------------------------------------------------------------------------
extern "C" void kernel_launch(void* const* d_in, const int* in_sizes, int n_in,
                              void* d_out, int out_size)
{
    const float* x      = (const float*)d_in[0];
    const float* Wq     = (const float*)d_in[1];
    const float* bq     = (const float*)d_in[2];
    const float* Wk     = (const float*)d_in[3];
    const float* bk     = (const float*)d_in[4];
    const float* Wv     = (const float*)d_in[5];
    const float* bv     = (const float*)d_in[6];
    const float* Wo     = (const float*)d_in[7];
    const float* bo     = (const float*)d_in[8];
    const float* spiral = (const float*)d_in[9];
    const float* rot    = (const float*)d_in[10];
    float* out = (float*)d_out;

    float *Qp, *Kp, *Vp, *Ap, *Xp, *Wqp, *Wkp, *Wvp, *Wop;
    cudaGetSymbolAddress((void**)&Qp, g_Q);
    cudaGetSymbolAddress((void**)&Kp, g_K);
    cudaGetSymbolAddress((void**)&Vp, g_V);
    cudaGetSymbolAddress((void**)&Ap, g_A);
    cudaGetSymbolAddress((void**)&Xp, g_X);
    cudaGetSymbolAddress((void**)&Wqp, g_Wq);
    cudaGetSymbolAddress((void**)&Wkp, g_Wk);
    cudaGetSymbolAddress((void**)&Wvp, g_Wv);
    cudaGetSymbolAddress((void**)&Wop, g_Wo);

    const int M = BATCH * SEQ;
    dim3 gg(DIM / 128, M / 128);
    const int xe4 = MTOT * DIM / 4, we4 = DIM * DIM / 4;

    cudaFuncSetAttribute(gemm_tf32_kernel,
                         cudaFuncAttributeMaxDynamicSharedMemorySize, GEMM_SMEM_BYTES);
    cudaFuncSetAttribute(flash_tf32_kernel,
                         cudaFuncAttributeMaxDynamicSharedMemorySize, FLASH_SMEM_BYTES);

    round_tf32_kernel<<<(xe4 + 255) / 256, 256>>>(x, Xp, xe4);
    round_tf32_kernel<<<(we4 + 255) / 256, 256>>>(Wq, Wqp, we4);
    round_tf32_kernel<<<(we4 + 255) / 256, 256>>>(Wk, Wkp, we4);
    round_tf32_kernel<<<(we4 + 255) / 256, 256>>>(Wv, Wvp, we4);
    round_tf32_kernel<<<(we4 + 255) / 256, 256>>>(Wo, Wop, we4);

    gemm_tf32_kernel<<<gg, 256, GEMM_SMEM_BYTES>>>(Xp, Wqp, bq, rot, 1, 1, Qp);
    gemm_tf32_kernel<<<gg, 256, GEMM_SMEM_BYTES>>>(Xp, Wkp, bk, rot, 2, 1, Kp);
    gemm_tf32_kernel<<<gg, 256, GEMM_SMEM_BYTES>>>(Xp, Wvp, bv, nullptr, 0, 1, Vp);

    flash_tf32_kernel<<<dim3(SEQ / 128, NH, BATCH), 256, FLASH_SMEM_BYTES>>>(
        Qp, Kp, Vp, spiral, Ap);

    gemm_tf32_kernel<<<gg, 256, GEMM_SMEM_BYTES>>>(Ap, Wop, bo, nullptr, 0, 0, out);
}

// round 12
// speedup vs baseline: 1.2512x; 1.2018x over previous
#include <cuda_runtime.h>
#include <math.h>
#include <stdint.h>

#define BATCH 4
#define SEQ   2048
#define DIM   2048
#define NH    16
#define DHEAD 128
#define MTOT  (BATCH * SEQ)

// Scratch (allocation-free rule: __device__ globals)
__device__ float g_Q[BATCH * SEQ * DIM];
__device__ float g_K[BATCH * SEQ * DIM];
__device__ float g_V[BATCH * SEQ * DIM];
__device__ float g_A[BATCH * SEQ * DIM];
__device__ float g_X[MTOT * DIM];
__device__ float g_Wq[DIM * DIM];
__device__ float g_Wk[DIM * DIM];
__device__ float g_Wv[DIM * DIM];
__device__ float g_Wo[DIM * DIM];

__device__ __forceinline__ unsigned f2tf32(float x) {
    unsigned u;
    asm("cvt.rna.tf32.f32 %0, %1;" : "=r"(u) : "f"(x));
    return u;
}
__device__ __forceinline__ void mma_tf32(float* d, const unsigned* a, const unsigned* b) {
    asm volatile(
        "mma.sync.aligned.m16n8k8.row.col.f32.tf32.tf32.f32 "
        "{%0,%1,%2,%3}, {%4,%5,%6,%7}, {%8,%9}, {%0,%1,%2,%3};\n"
        : "+f"(d[0]), "+f"(d[1]), "+f"(d[2]), "+f"(d[3])
        : "r"(a[0]), "r"(a[1]), "r"(a[2]), "r"(a[3]), "r"(b[0]), "r"(b[1]));
}

// ---------------------------------------------------------------------------
// elementwise tf32-RNA rounding
// ---------------------------------------------------------------------------
__global__ __launch_bounds__(256) void round_tf32_kernel(
    const float* __restrict__ in, float* __restrict__ out, int n4)
{
    int i = blockIdx.x * blockDim.x + threadIdx.x;
    if (i >= n4) return;
    float4 v = ((const float4*)in)[i];
    uint4 u = make_uint4(f2tf32(v.x), f2tf32(v.y), f2tf32(v.z), f2tf32(v.w));
    ((uint4*)out)[i] = u;
}

// ---------------------------------------------------------------------------
// TF32 NT GEMM (R6 structure: register double-buffer, one sync per k-tile).
// Inputs MUST be tf32-pre-rounded; R2S is a pure copy.
// Fused over up to 3 weight matrices via blockIdx.x = z*16 + nx.
// C[z] = (A @ W[z]^T + bias[z]) * gate(mode[z])
// ---------------------------------------------------------------------------
#define GSTRIDE 36
#define GBUF (128 * GSTRIDE)
#define GEMM_SMEM_BYTES (4 * GBUF * 4)   // 73728 -> 2 CTAs/SM

struct GemmArgs {
    const float* W[3];
    const float* bias[3];
    float*       C[3];
    int          mode[3];     // 0 none, 1 cos, 2 sin
    int          roundout;
};

__global__ __launch_bounds__(256) void gemm_tf32_kernel(
    const float* __restrict__ A, const float* __restrict__ rot, GemmArgs args)
{
    extern __shared__ unsigned sm[];
    unsigned* As = sm;
    unsigned* Bs = sm + 2 * GBUF;

    const int K = DIM, N = DIM;
    const int tid = threadIdx.x;
    const int warp = tid >> 5, lane = tid & 31;
    const int wm = (warp >> 2) * 64;
    const int wn = (warp & 3) * 32;
    const int z = blockIdx.x >> 4;
    const int bm = blockIdx.y * 128, bn = (blockIdx.x & 15) * 128;

    const float* __restrict__ W    = args.W[z];
    const float* __restrict__ bias = args.bias[z];
    float*       __restrict__ C    = args.C[z];
    const int mode = args.mode[z];

    const int lrow = tid >> 3;          // 0..31
    const int lcol = (tid & 7) * 4;     // 0..28

    float acc[4][4][4];
#pragma unroll
    for (int i = 0; i < 4; i++)
#pragma unroll
        for (int j = 0; j < 4; j++)
#pragma unroll
            for (int t = 0; t < 4; t++) acc[i][j][t] = 0.f;

    const float* Ag = A + (size_t)(bm + lrow) * K + lcol;
    const float* Wg = W + (size_t)(bn + lrow) * K + lcol;

    float4 ra[4], rb[4];

    auto G2R = [&](int kt) {
        const size_t ko = (size_t)kt * 32;
#pragma unroll
        for (int it = 0; it < 4; it++) {
            ra[it] = *(const float4*)(Ag + (size_t)it * 32 * K + ko);
            rb[it] = *(const float4*)(Wg + (size_t)it * 32 * K + ko);
        }
    };
    auto R2S = [&](int buf) {
#pragma unroll
        for (int it = 0; it < 4; it++) {
            int base = buf * GBUF + (lrow + it * 32) * GSTRIDE + lcol;
            *(float4*)(As + base) = ra[it];
            *(float4*)(Bs + base) = rb[it];
        }
    };

    const int ntiles = K / 32;   // 64
    G2R(0);
    R2S(0);
    __syncthreads();

    const int lq = lane >> 2;
    const int lr = lane & 3;

    for (int kt = 0; kt < ntiles; kt++) {
        if (kt + 1 < ntiles) G2R(kt + 1);

        const unsigned* Ab = As + (kt & 1) * GBUF;
        const unsigned* Bb = Bs + (kt & 1) * GBUF;
#pragma unroll
        for (int k8 = 0; k8 < 4; k8++) {
            const int kc = k8 * 8 + lr;
            unsigned af[4][4], bf[4][2];
#pragma unroll
            for (int i = 0; i < 4; i++) {
                int r = wm + i * 16 + lq;
                af[i][0] = Ab[r * GSTRIDE + kc];
                af[i][1] = Ab[(r + 8) * GSTRIDE + kc];
                af[i][2] = Ab[r * GSTRIDE + kc + 4];
                af[i][3] = Ab[(r + 8) * GSTRIDE + kc + 4];
            }
#pragma unroll
            for (int j = 0; j < 4; j++) {
                int c = wn + j * 8 + lq;
                bf[j][0] = Bb[c * GSTRIDE + kc];
                bf[j][1] = Bb[c * GSTRIDE + kc + 4];
            }
#pragma unroll
            for (int i = 0; i < 4; i++)
#pragma unroll
                for (int j = 0; j < 4; j++)
                    mma_tf32(acc[i][j], af[i], bf[j]);
        }

        if (kt + 1 < ntiles) R2S((kt + 1) & 1);
        __syncthreads();
    }

    // epilogue: bias + optional cos/sin gate, optional tf32 rounding
#pragma unroll
    for (int j = 0; j < 4; j++) {
        int c0 = bn + wn + j * 8 + (lr << 1);
        float b0 = __ldg(bias + c0), b1 = __ldg(bias + c0 + 1);
        float g0 = 1.f, g1 = 1.f;
        if (mode == 1) { g0 = cosf(__ldg(rot + c0)); g1 = cosf(__ldg(rot + c0 + 1)); }
        else if (mode == 2) { g0 = sinf(__ldg(rot + c0)); g1 = sinf(__ldg(rot + c0 + 1)); }
#pragma unroll
        for (int i = 0; i < 4; i++) {
            int r0 = bm + wm + i * 16 + lq;
            float v00 = (acc[i][j][0] + b0) * g0, v01 = (acc[i][j][1] + b1) * g1;
            float v10 = (acc[i][j][2] + b0) * g0, v11 = (acc[i][j][3] + b1) * g1;
            if (args.roundout) {
                v00 = __uint_as_float(f2tf32(v00)); v01 = __uint_as_float(f2tf32(v01));
                v10 = __uint_as_float(f2tf32(v10)); v11 = __uint_as_float(f2tf32(v11));
            }
            *(float2*)(C + (size_t)r0 * N + c0)       = make_float2(v00, v01);
            *(float2*)(C + (size_t)(r0 + 8) * N + c0) = make_float2(v10, v11);
        }
    }
}

// ---------------------------------------------------------------------------
// TF32 mma.sync flash attention (R6 known-good; output tf32-rounded for the
// pre-rounded final GEMM — numerically identical to R6's in-GEMM cvt).
// BM=64 (4 warps x 16 rows), BN=64, DH=128, 128 threads, 2 CTAs/SM.
// ---------------------------------------------------------------------------
#define KSTRIDE 132
#define FLASH_SMEM_BYTES (2 * 64 * KSTRIDE * 4)

__global__ __launch_bounds__(128) void flash_tf32_kernel(
    const float* __restrict__ Q, const float* __restrict__ K,
    const float* __restrict__ V, const float* __restrict__ spiral,
    float* __restrict__ O)
{
    extern __shared__ float fs[];
    float* sK = fs;
    float* sV = fs + 64 * KSTRIDE;

    const int tid = threadIdx.x;
    const int warp = tid >> 5, lane = tid & 31;
    const int lq = lane >> 2, lr = lane & 3;
    const int qt = blockIdx.x, h = blockIdx.y, b = blockIdx.z;
    const int s0 = qt * 64;
    const float scale = spiral[h] * 0.08838834764831845f;

    const size_t baseQ = ((size_t)b * SEQ + s0) * DIM + (size_t)h * DHEAD;
    const size_t baseK = (size_t)b * SEQ * DIM + (size_t)h * DHEAD;

    for (int idx = tid; idx < 64 * 32; idx += 128) {
        int r = idx >> 5, c4 = (idx & 31) << 2;
        *(float4*)(sK + r * KSTRIDE + c4) =
            *(const float4*)(Q + baseQ + (size_t)r * DIM + c4);
    }
    __syncthreads();

    unsigned qf[16][4];
    const int qrow = warp * 16 + lq;
#pragma unroll
    for (int ks = 0; ks < 16; ks++) {
        qf[ks][0] = __float_as_uint(sK[qrow * KSTRIDE + ks * 8 + lr]);
        qf[ks][1] = __float_as_uint(sK[(qrow + 8) * KSTRIDE + ks * 8 + lr]);
        qf[ks][2] = __float_as_uint(sK[qrow * KSTRIDE + ks * 8 + lr + 4]);
        qf[ks][3] = __float_as_uint(sK[(qrow + 8) * KSTRIDE + ks * 8 + lr + 4]);
    }
    __syncthreads();

    float o[16][4];
#pragma unroll
    for (int jn = 0; jn < 16; jn++)
#pragma unroll
        for (int t = 0; t < 4; t++) o[jn][t] = 0.f;
    float m0 = -INFINITY, m1 = -INFINITY, l0 = 0.f, l1 = 0.f;

    for (int kt = 0; kt < SEQ / 64; kt++) {
        const size_t kb = baseK + (size_t)kt * 64 * DIM;
        for (int idx = tid; idx < 64 * 32; idx += 128) {
            int r = idx >> 5, c4 = (idx & 31) << 2;
            *(float4*)(sK + r * KSTRIDE + c4) =
                *(const float4*)(K + kb + (size_t)r * DIM + c4);
            *(float4*)(sV + r * KSTRIDE + c4) =
                *(const float4*)(V + kb + (size_t)r * DIM + c4);
        }
        __syncthreads();

        float sacc[8][4];
#pragma unroll
        for (int j = 0; j < 8; j++)
#pragma unroll
            for (int t = 0; t < 4; t++) sacc[j][t] = 0.f;

#pragma unroll
        for (int ks = 0; ks < 16; ks++) {
#pragma unroll
            for (int j = 0; j < 8; j++) {
                unsigned bf[2];
                bf[0] = __float_as_uint(sK[(j * 8 + lq) * KSTRIDE + ks * 8 + lr]);
                bf[1] = __float_as_uint(sK[(j * 8 + lq) * KSTRIDE + ks * 8 + lr + 4]);
                mma_tf32(sacc[j], qf[ks], bf);
            }
        }

        float mx0 = -INFINITY, mx1 = -INFINITY;
#pragma unroll
        for (int j = 0; j < 8; j++) {
            sacc[j][0] *= scale; sacc[j][1] *= scale;
            sacc[j][2] *= scale; sacc[j][3] *= scale;
            mx0 = fmaxf(mx0, fmaxf(sacc[j][0], sacc[j][1]));
            mx1 = fmaxf(mx1, fmaxf(sacc[j][2], sacc[j][3]));
        }
        mx0 = fmaxf(mx0, __shfl_xor_sync(0xffffffffu, mx0, 1));
        mx0 = fmaxf(mx0, __shfl_xor_sync(0xffffffffu, mx0, 2));
        mx1 = fmaxf(mx1, __shfl_xor_sync(0xffffffffu, mx1, 1));
        mx1 = fmaxf(mx1, __shfl_xor_sync(0xffffffffu, mx1, 2));

        float mn0 = fmaxf(m0, mx0), mn1 = fmaxf(m1, mx1);
        float al0 = __expf(m0 - mn0), al1 = __expf(m1 - mn1);
        m0 = mn0; m1 = mn1;

        unsigned pb[8][4];
        float sum0 = 0.f, sum1 = 0.f;
#pragma unroll
        for (int j = 0; j < 8; j++) {
            float p0 = __expf(sacc[j][0] - mn0);
            float p1 = __expf(sacc[j][1] - mn0);
            float p2 = __expf(sacc[j][2] - mn1);
            float p3 = __expf(sacc[j][3] - mn1);
            sum0 += p0 + p1; sum1 += p2 + p3;
            pb[j][0] = f2tf32(p0); pb[j][1] = f2tf32(p1);
            pb[j][2] = f2tf32(p2); pb[j][3] = f2tf32(p3);
        }
        sum0 += __shfl_xor_sync(0xffffffffu, sum0, 1);
        sum0 += __shfl_xor_sync(0xffffffffu, sum0, 2);
        sum1 += __shfl_xor_sync(0xffffffffu, sum1, 1);
        sum1 += __shfl_xor_sync(0xffffffffu, sum1, 2);
        l0 = l0 * al0 + sum0;
        l1 = l1 * al1 + sum1;

#pragma unroll
        for (int jn = 0; jn < 16; jn++) {
            o[jn][0] *= al0; o[jn][1] *= al0;
            o[jn][2] *= al1; o[jn][3] *= al1;
        }

        const int srcl = lq * 4 + (lr >> 1);
#pragma unroll
        for (int k8 = 0; k8 < 8; k8++) {
            unsigned a[4];
            unsigned t00 = __shfl_sync(0xffffffffu, pb[k8][0], srcl);
            unsigned t01 = __shfl_sync(0xffffffffu, pb[k8][1], srcl);
            unsigned t10 = __shfl_sync(0xffffffffu, pb[k8][2], srcl);
            unsigned t11 = __shfl_sync(0xffffffffu, pb[k8][3], srcl);
            unsigned u00 = __shfl_sync(0xffffffffu, pb[k8][0], srcl + 2);
            unsigned u01 = __shfl_sync(0xffffffffu, pb[k8][1], srcl + 2);
            unsigned u10 = __shfl_sync(0xffffffffu, pb[k8][2], srcl + 2);
            unsigned u11 = __shfl_sync(0xffffffffu, pb[k8][3], srcl + 2);
            a[0] = (lr & 1) ? t01 : t00;
            a[1] = (lr & 1) ? t11 : t10;
            a[2] = (lr & 1) ? u01 : u00;
            a[3] = (lr & 1) ? u11 : u10;
#pragma unroll
            for (int jn = 0; jn < 16; jn++) {
                unsigned bf[2];
                bf[0] = __float_as_uint(sV[(k8 * 8 + lr) * KSTRIDE + jn * 8 + lq]);
                bf[1] = __float_as_uint(sV[(k8 * 8 + lr + 4) * KSTRIDE + jn * 8 + lq]);
                mma_tf32(o[jn], a, bf);
            }
        }
        __syncthreads();
    }

    const float inv0 = 1.0f / l0, inv1 = 1.0f / l1;
    float* Orow0 = O + baseQ + (size_t)qrow * DIM;
    float* Orow1 = O + baseQ + (size_t)(qrow + 8) * DIM;
#pragma unroll
    for (int jn = 0; jn < 16; jn++) {
        int c = jn * 8 + 2 * lr;
        float2 a0 = make_float2(__uint_as_float(f2tf32(o[jn][0] * inv0)),
                                __uint_as_float(f2tf32(o[jn][1] * inv0)));
        float2 a1 = make_float2(__uint_as_float(f2tf32(o[jn][2] * inv1)),
                                __uint_as_float(f2tf32(o[jn][3] * inv1)));
        *(float2*)(Orow0 + c) = a0;
        *(float2*)(Orow1 + c) = a1;
    }
}

// ---------------------------------------------------------------------------
extern "C" void kernel_launch(void* const* d_in, const int* in_sizes, int n_in,
                              void* d_out, int out_size)
{
    const float* x      = (const float*)d_in[0];
    const float* Wq     = (const float*)d_in[1];
    const float* bq     = (const float*)d_in[2];
    const float* Wk     = (const float*)d_in[3];
    const float* bk     = (const float*)d_in[4];
    const float* Wv     = (const float*)d_in[5];
    const float* bv     = (const float*)d_in[6];
    const float* Wo     = (const float*)d_in[7];
    const float* bo     = (const float*)d_in[8];
    const float* spiral = (const float*)d_in[9];
    const float* rot    = (const float*)d_in[10];
    float* out = (float*)d_out;

    float *Qp, *Kp, *Vp, *Ap, *Xp, *Wqp, *Wkp, *Wvp, *Wop;
    cudaGetSymbolAddress((void**)&Qp, g_Q);
    cudaGetSymbolAddress((void**)&Kp, g_K);
    cudaGetSymbolAddress((void**)&Vp, g_V);
    cudaGetSymbolAddress((void**)&Ap, g_A);
    cudaGetSymbolAddress((void**)&Xp, g_X);
    cudaGetSymbolAddress((void**)&Wqp, g_Wq);
    cudaGetSymbolAddress((void**)&Wkp, g_Wk);
    cudaGetSymbolAddress((void**)&Wvp, g_Wv);
    cudaGetSymbolAddress((void**)&Wop, g_Wo);

    const int M = BATCH * SEQ;
    const int xe4 = MTOT * DIM / 4, we4 = DIM * DIM / 4;

    cudaFuncSetAttribute(gemm_tf32_kernel,
                         cudaFuncAttributeMaxDynamicSharedMemorySize, GEMM_SMEM_BYTES);
    cudaFuncSetAttribute(flash_tf32_kernel,
                         cudaFuncAttributeMaxDynamicSharedMemorySize, FLASH_SMEM_BYTES);

    // pre-round inputs to tf32 (RNA) once
    round_tf32_kernel<<<(xe4 + 255) / 256, 256>>>(x, Xp, xe4);
    round_tf32_kernel<<<(we4 + 255) / 256, 256>>>(Wq, Wqp, we4);
    round_tf32_kernel<<<(we4 + 255) / 256, 256>>>(Wk, Wkp, we4);
    round_tf32_kernel<<<(we4 + 255) / 256, 256>>>(Wv, Wvp, we4);
    round_tf32_kernel<<<(we4 + 255) / 256, 256>>>(Wo, Wop, we4);

    // fused QKV projection: z = blockIdx.x/16 selects weight/output
    {
        GemmArgs a;
        a.W[0] = Wqp;  a.W[1] = Wkp;  a.W[2] = Wvp;
        a.bias[0] = bq; a.bias[1] = bk; a.bias[2] = bv;
        a.C[0] = Qp;   a.C[1] = Kp;   a.C[2] = Vp;
        a.mode[0] = 1; a.mode[1] = 2; a.mode[2] = 0;
        a.roundout = 1;
        gemm_tf32_kernel<<<dim3(48, M / 128), 256, GEMM_SMEM_BYTES>>>(Xp, rot, a);
    }

    flash_tf32_kernel<<<dim3(SEQ / 64, NH, BATCH), 128, FLASH_SMEM_BYTES>>>(
        Qp, Kp, Vp, spiral, Ap);

    // output projection
    {
        GemmArgs a;
        a.W[0] = Wop;  a.W[1] = Wop;  a.W[2] = Wop;
        a.bias[0] = bo; a.bias[1] = bo; a.bias[2] = bo;
        a.C[0] = out;  a.C[1] = out;  a.C[2] = out;
        a.mode[0] = 0; a.mode[1] = 0; a.mode[2] = 0;
        a.roundout = 0;
        gemm_tf32_kernel<<<dim3(16, M / 128), 256, GEMM_SMEM_BYTES>>>(Ap, rot, a);
    }
}